// round 2
// baseline (speedup 1.0000x reference)
#include <cuda_runtime.h>
#include <cstdint>
#include <cmath>
#include <cstdlib>

// ---------------- static config ----------------
#define Bv 32
#define Cv 21
#define Pv 24
#define Ev 64
#define NB (Bv*Cv)          // 672 row-batches
#define SDEC 28
#define SENC 30
#define DMODEL 1536         // Pv*Ev
#define DFFv 3072
#define NH 8
#define DHh 192             // DMODEL/NH
#define MDEC (NB*SDEC)      // 18816 tokens
#define MENC (NB*SENC)      // 20160 tokens
#define LDEC 672            // decoder input length

// ---------------- device scratch (static, allocation-free) ----------------
__device__ float g_x   [(size_t)MDEC*DMODEL];
__device__ float g_xc  [(size_t)MENC*DMODEL];
__device__ float g_q   [(size_t)MDEC*DMODEL];
__device__ float g_k   [(size_t)MENC*DMODEL];
__device__ float g_v   [(size_t)MENC*DMODEL];
__device__ float g_attn[(size_t)MDEC*DMODEL];
__device__ float g_tmp [(size_t)MDEC*DMODEL];
__device__ float g_ffn [(size_t)MDEC*DFFv];

struct MaskParam { unsigned int rows[SDEC]; };

// ---------------- helpers ----------------
__device__ __forceinline__ float blockReduceSum(float val, float* sh) {
    int lane = threadIdx.x & 31;
    int wid  = threadIdx.x >> 5;
    #pragma unroll
    for (int o = 16; o > 0; o >>= 1) val += __shfl_down_sync(0xffffffffu, val, o);
    if (lane == 0) sh[wid] = val;
    __syncthreads();
    if (wid == 0) {
        float v2 = (lane < 8) ? sh[lane] : 0.f;   // 256 threads = 8 warps
        #pragma unroll
        for (int o = 4; o > 0; o >>= 1) v2 += __shfl_down_sync(0xffffffffu, v2, o);
        if (lane == 0) sh[0] = v2;
    }
    __syncthreads();
    float r = sh[0];
    __syncthreads();
    return r;
}

// ---------------- kernels ----------------

// cross (B,E,SENC,P,C) -> g_xc[(b*C+c), s, p*E+e]
__global__ void build_xc_kernel(const float* __restrict__ cross) {
    int idx = blockIdx.x * blockDim.x + threadIdx.x;
    const int total = MENC * DMODEL;
    if (idx >= total) return;
    int d = idx % DMODEL;
    int t = idx / DMODEL;
    int s = t % SENC;
    int n = t / SENC;
    int b = n / Cv, c = n % Cv;
    int p = d >> 6, e = d & 63;
    g_xc[idx] = cross[(size_t)b*(Ev*SENC*Pv*Cv) + (size_t)e*(SENC*Pv*Cv) + s*(Pv*Cv) + p*Cv + c];
}

// emb+pos rearrange + pre-LN -> g_x
__global__ void build_x_ln_kernel(const float* __restrict__ x_dec,
                                  const float* __restrict__ pos,
                                  const float* __restrict__ val_w,
                                  const float* __restrict__ val_b,
                                  const float* __restrict__ gam,
                                  const float* __restrict__ bet) {
    __shared__ float sh[32];
    int r = blockIdx.x;                 // token row 0..MDEC-1
    int s = r % SDEC, n = r / SDEC;
    int b = n / Cv, c = n % Cv;
    int tid = threadIdx.x;
    float v[6];
    float sum = 0.f;
    #pragma unroll
    for (int q = 0; q < 6; q++) {
        int d = tid + q*256;
        int p = d >> 6, e = d & 63;
        float xd  = x_dec[(size_t)b*(LDEC*Cv) + (s*Pv + p)*Cv + c];
        float emb = xd * val_w[e] + val_b[e];
        float ps  = pos[(size_t)e*(SDEC*Pv*Cv) + s*(Pv*Cv) + p*Cv + c];
        v[q] = emb + ps;
        sum += v[q];
    }
    float mean = blockReduceSum(sum, sh) * (1.f/DMODEL);
    float vs = 0.f;
    #pragma unroll
    for (int q = 0; q < 6; q++) { float d0 = v[q]-mean; vs += d0*d0; }
    float var = blockReduceSum(vs, sh) * (1.f/DMODEL);
    float inv = rsqrtf(var + 1e-5f);
    #pragma unroll
    for (int q = 0; q < 6; q++) {
        int d = tid + q*256;
        g_x[(size_t)r*DMODEL + d] = (v[q]-mean)*inv*gam[d] + bet[d];
    }
}

// X = LN(X + Y, g, b)   (per token row)
__global__ void add_ln_kernel(float* __restrict__ X, const float* __restrict__ Y,
                              const float* __restrict__ gam, const float* __restrict__ bet) {
    __shared__ float sh[32];
    int r = blockIdx.x, tid = threadIdx.x;
    float v[6]; float sum = 0.f;
    #pragma unroll
    for (int q = 0; q < 6; q++) {
        int d = tid + q*256;
        v[q] = X[(size_t)r*DMODEL + d] + Y[(size_t)r*DMODEL + d];
        sum += v[q];
    }
    float mean = blockReduceSum(sum, sh) * (1.f/DMODEL);
    float vs = 0.f;
    #pragma unroll
    for (int q = 0; q < 6; q++) { float d0 = v[q]-mean; vs += d0*d0; }
    float var = blockReduceSum(vs, sh) * (1.f/DMODEL);
    float inv = rsqrtf(var + 1e-5f);
    #pragma unroll
    for (int q = 0; q < 6; q++) {
        int d = tid + q*256;
        X[(size_t)r*DMODEL + d] = (v[q]-mean)*inv*gam[d] + bet[d];
    }
}

// X = LN( LN(X+Y, g3,b3), fg, fb )
__global__ void add_ln2_kernel(float* __restrict__ X, const float* __restrict__ Y,
                               const float* __restrict__ g3, const float* __restrict__ b3,
                               const float* __restrict__ fg, const float* __restrict__ fb) {
    __shared__ float sh[32];
    int r = blockIdx.x, tid = threadIdx.x;
    float v[6]; float sum = 0.f;
    #pragma unroll
    for (int q = 0; q < 6; q++) {
        int d = tid + q*256;
        v[q] = X[(size_t)r*DMODEL + d] + Y[(size_t)r*DMODEL + d];
        sum += v[q];
    }
    float mean = blockReduceSum(sum, sh) * (1.f/DMODEL);
    float vs = 0.f;
    #pragma unroll
    for (int q = 0; q < 6; q++) { float d0 = v[q]-mean; vs += d0*d0; }
    float var = blockReduceSum(vs, sh) * (1.f/DMODEL);
    float inv = rsqrtf(var + 1e-5f);
    float sum2 = 0.f;
    #pragma unroll
    for (int q = 0; q < 6; q++) {
        int d = tid + q*256;
        v[q] = (v[q]-mean)*inv*g3[d] + b3[d];
        sum2 += v[q];
    }
    float mean2 = blockReduceSum(sum2, sh) * (1.f/DMODEL);
    float vs2 = 0.f;
    #pragma unroll
    for (int q = 0; q < 6; q++) { float d0 = v[q]-mean2; vs2 += d0*d0; }
    float var2 = blockReduceSum(vs2, sh) * (1.f/DMODEL);
    float inv2 = rsqrtf(var2 + 1e-5f);
    #pragma unroll
    for (int q = 0; q < 6; q++) {
        int d = tid + q*256;
        X[(size_t)r*DMODEL + d] = (v[q]-mean2)*inv2*fg[d] + fb[d];
    }
}

// out[b,e,s,p,c] = x_final + identity(emb without pos)
__global__ void out_kernel(const float* __restrict__ x_dec,
                           const float* __restrict__ val_w,
                           const float* __restrict__ val_b,
                           float* __restrict__ out) {
    int idx = blockIdx.x * blockDim.x + threadIdx.x;
    const int total = Bv*Ev*SDEC*Pv*Cv;
    if (idx >= total) return;
    int c = idx % Cv;
    int p = (idx / Cv) % Pv;
    int s = (idx / (Cv*Pv)) % SDEC;
    int e = (idx / (Cv*Pv*SDEC)) % Ev;
    int b =  idx / (Cv*Pv*SDEC*Ev);
    int n = b*Cv + c;
    float xf  = g_x[(size_t)(n*SDEC + s)*DMODEL + p*Ev + e];
    float emb = x_dec[(size_t)b*(LDEC*Cv) + (s*Pv + p)*Cv + c] * val_w[e] + val_b[e];
    out[idx] = xf + emb;
}

// generic fp32 GEMM: C[M,N] = A[M,K] @ W[K,N] + bias ; ACT=1 -> tanh GELU
template<int ACT>
__global__ void __launch_bounds__(256,2) sgemm_kernel(
    const float* __restrict__ A, const float* __restrict__ W,
    const float* __restrict__ bias, float* __restrict__ C,
    int M, int N, int K)
{
    const int BK = 16;
    __shared__ float As[16][128];
    __shared__ float Bs[16][128];
    const int tid = threadIdx.x;
    const int m0 = blockIdx.y * 128;
    const int n0 = blockIdx.x * 128;
    const int tx = tid & 15;
    const int ty = tid >> 4;
    const int trow = ty * 8;
    const int tcol = tx * 8;
    float acc[8][8];
    #pragma unroll
    for (int i = 0; i < 8; i++)
        #pragma unroll
        for (int j = 0; j < 8; j++) acc[i][j] = 0.f;

    const int arow = tid >> 2;         // 0..63
    const int acol = (tid & 3) << 2;   // 0,4,8,12
    const int brow = tid >> 5;         // 0..7
    const int bcol = (tid & 31) << 2;  // 0..124

    for (int k0 = 0; k0 < K; k0 += BK) {
        #pragma unroll
        for (int pp = 0; pp < 2; pp++) {
            int r  = arow + pp*64;
            int gm = m0 + r;
            float4 va;
            if (gm < M) va = *reinterpret_cast<const float4*>(A + (size_t)gm*K + k0 + acol);
            else        va = make_float4(0.f, 0.f, 0.f, 0.f);
            As[acol+0][r] = va.x; As[acol+1][r] = va.y;
            As[acol+2][r] = va.z; As[acol+3][r] = va.w;
        }
        #pragma unroll
        for (int pp = 0; pp < 2; pp++) {
            int r = brow + pp*8;
            float4 vb = *reinterpret_cast<const float4*>(W + (size_t)(k0+r)*N + n0 + bcol);
            *reinterpret_cast<float4*>(&Bs[r][bcol]) = vb;
        }
        __syncthreads();
        #pragma unroll
        for (int kk = 0; kk < BK; kk++) {
            float ar[8], br[8];
            #pragma unroll
            for (int i = 0; i < 8; i++) ar[i] = As[kk][trow+i];
            #pragma unroll
            for (int j = 0; j < 8; j++) br[j] = Bs[kk][tcol+j];
            #pragma unroll
            for (int i = 0; i < 8; i++)
                #pragma unroll
                for (int j = 0; j < 8; j++)
                    acc[i][j] = fmaf(ar[i], br[j], acc[i][j]);
        }
        __syncthreads();
    }
    #pragma unroll
    for (int i = 0; i < 8; i++) {
        int gm = m0 + trow + i;
        if (gm >= M) break;
        #pragma unroll
        for (int j4 = 0; j4 < 8; j4 += 4) {
            float4 v; float* vp = &v.x;
            #pragma unroll
            for (int q = 0; q < 4; q++) {
                float val = acc[i][j4+q] + bias[n0 + tcol + j4 + q];
                if (ACT == 1) {
                    float xx = val;
                    val = 0.5f*xx*(1.f + tanhf(0.7978845608028654f*(xx + 0.044715f*xx*xx*xx)));
                }
                vp[q] = val;
            }
            *reinterpret_cast<float4*>(C + (size_t)gm*N + n0 + tcol + j4) = v;
        }
    }
}

// sparse attention for one (n, h); LK = 28 (self) or 30 (cross)
template<int LK>
__global__ void __launch_bounds__(256) attn_kernel(
    const float* __restrict__ Q, const float* __restrict__ Km,
    const float* __restrict__ Vm, float* __restrict__ O, MaskParam mask)
{
    __shared__ float qs[DHh][SDEC];     // transposed for conflict-free score reads
    __shared__ float ks[LK][DHh];
    __shared__ float sc[SDEC][32];
    int n = blockIdx.x, h = blockIdx.y, tid = threadIdx.x;
    const float* qb = Q  + (size_t)n*SDEC*DMODEL + h*DHh;
    const float* kb = Km + (size_t)n*LK  *DMODEL + h*DHh;
    const float* vb = Vm + (size_t)n*LK  *DMODEL + h*DHh;

    for (int idx = tid; idx < SDEC*DHh; idx += 256) {
        int i = idx / DHh, d = idx % DHh;
        qs[d][i] = qb[(size_t)i*DMODEL + d];
    }
    for (int idx = tid; idx < LK*DHh; idx += 256) {
        int j = idx / DHh, d = idx % DHh;
        ks[j][d] = kb[(size_t)j*DMODEL + d];
    }
    __syncthreads();

    const float scale = 0.07216878364870323f;   // 1/sqrt(192)
    for (int idx = tid; idx < SDEC*LK; idx += 256) {
        int i = idx % SDEC, j = idx / SDEC;
        float s = 0.f;
        #pragma unroll 16
        for (int d = 0; d < DHh; d++) s += qs[d][i] * ks[j][d];
        bool mm = (mask.rows[i] >> j) & 1u;
        sc[i][j] = mm ? s*scale : -1e9f;
    }
    __syncthreads();

    if (tid < SDEC) {
        float mx = -3.0e38f;
        #pragma unroll
        for (int j = 0; j < LK; j++) mx = fmaxf(mx, sc[tid][j]);
        float ssum = 0.f;
        #pragma unroll
        for (int j = 0; j < LK; j++) { float e0 = expf(sc[tid][j]-mx); sc[tid][j] = e0; ssum += e0; }
        float invs = 1.f/ssum;
        #pragma unroll
        for (int j = 0; j < LK; j++) sc[tid][j] *= invs;
    }
    __syncthreads();

    for (int idx = tid; idx < SDEC*DHh; idx += 256) {
        int i = idx / DHh, d = idx % DHh;
        float o = 0.f;
        #pragma unroll
        for (int j = 0; j < LK; j++) o += sc[i][j] * vb[(size_t)j*DMODEL + d];
        O[(size_t)(n*SDEC + i)*DMODEL + h*DHh + d] = o;
    }
}

// ---------------- host: numpy default_rng(seed).random() bit-exact ----------------
typedef unsigned __int128 u128;
struct PCG64H { u128 state, inc; };
static inline void pcg_step(PCG64H& r) {
    const u128 MULT = (((u128)0x2360ed051fc65da4ULL) << 64) | 0x4385df649fccf645ULL;
    r.state = r.state * MULT + r.inc;
}
static inline uint64_t pcg_next(PCG64H& r) {
    pcg_step(r);
    uint64_t xored = (uint64_t)(r.state >> 64) ^ (uint64_t)r.state;
    unsigned rot = (unsigned)(r.state >> 122);
    return (xored >> rot) | (xored << ((64u - rot) & 63u));
}
static void np_seed_pcg(uint32_t seed_word, PCG64H& r) {
    // SeedSequence pool mix
    const uint32_t INIT_A = 0x43b0d7e5u, MULT_A = 0x931e8875u;
    const uint32_t INIT_B = 0x8b51f9ddu, MULT_B = 0x58f38dedu;
    const uint32_t MIX_L  = 0xca01f9ddu, MIX_R  = 0x4973f715u;
    uint32_t hc = INIT_A;
    uint32_t pool[4];
    auto hashmix = [&hc, MULT_A](uint32_t v) -> uint32_t {
        v ^= hc; hc *= MULT_A; v *= hc; v ^= v >> 16; return v;
    };
    auto mix = [MIX_L, MIX_R](uint32_t x, uint32_t y) -> uint32_t {
        uint32_t res = x*MIX_L - y*MIX_R; res ^= res >> 16; return res;
    };
    pool[0] = hashmix(seed_word);
    for (int i = 1; i < 4; i++) pool[i] = hashmix(0u);
    for (int s = 0; s < 4; s++)
        for (int d = 0; d < 4; d++)
            if (s != d) pool[d] = mix(pool[d], hashmix(pool[s]));
    // generate_state(4, uint64) -> 8 uint32 words
    uint32_t st[8]; uint32_t hc2 = INIT_B;
    for (int i = 0; i < 8; i++) {
        uint32_t v = pool[i & 3];
        v ^= hc2; hc2 *= MULT_B; v *= hc2; v ^= v >> 16;
        st[i] = v;
    }
    uint64_t w[4];
    for (int i = 0; i < 4; i++) w[i] = (uint64_t)st[2*i] | ((uint64_t)st[2*i+1] << 32);
    // pcg64_set_seed: s = (w0<<64)|w1 ; inc = (w2<<64)|w3
    u128 initstate = (((u128)w[0]) << 64) | w[1];
    u128 initseq   = (((u128)w[2]) << 64) | w[3];
    r.state = 0; r.inc = (initseq << 1) | 1;
    pcg_step(r);
    r.state += initstate;
    pcg_step(r);
}
static void build_mask_host(int Lq, int Lk, uint32_t seed, unsigned int* rows) {
    PCG64H r; np_seed_pcg(seed, r);
    int off = Lk - Lq;
    for (int i = 0; i < Lq; i++) {
        unsigned int m = 0;
        for (int j = 0; j < Lk; j++) {
            double dv = (double)(pcg_next(r) >> 11) * (1.0/9007199254740992.0);
            int a = i + off - j; if (a < 0) a = -a;
            bool loc = (a <= 3);
            bool str = ((j & 3) == 0);
            bool rnd = (dv < 0.1);
            if (loc || str || rnd) m |= (1u << j);
        }
        rows[i] = m;
    }
}

// ---------------- launch ----------------
extern "C" void kernel_launch(void* const* d_in, const int* in_sizes, int n_in,
                              void* d_out, int out_size) {
    const float* x_dec = (const float*)d_in[0];
    const float* cross = (const float*)d_in[1];
    const float* val_w = (const float*)d_in[2];
    const float* val_b = (const float*)d_in[3];
    const float* pos   = (const float*)d_in[4];
    const float* pre_g = (const float*)d_in[5];
    const float* pre_b = (const float*)d_in[6];
    const float* Wq = (const float*)d_in[7];
    const float* bq = (const float*)d_in[8];
    const float* Wk = (const float*)d_in[9];
    const float* bk = (const float*)d_in[10];
    const float* Wv = (const float*)d_in[11];
    const float* bv = (const float*)d_in[12];
    const float* Wo = (const float*)d_in[13];
    const float* bo = (const float*)d_in[14];
    const float* n1g = (const float*)d_in[15];
    const float* n1b = (const float*)d_in[16];
    const float* n2g = (const float*)d_in[17];
    const float* n2b = (const float*)d_in[18];
    const float* n3g = (const float*)d_in[19];
    const float* n3b = (const float*)d_in[20];
    const float* W1 = (const float*)d_in[21];
    const float* b1 = (const float*)d_in[22];
    const float* W2 = (const float*)d_in[23];
    const float* b2 = (const float*)d_in[24];
    const float* fg = (const float*)d_in[25];
    const float* fb = (const float*)d_in[26];
    float* out = (float*)d_out;

    static float *px=nullptr, *pxc=nullptr, *pq=nullptr, *pk=nullptr, *pv=nullptr,
                 *pattn=nullptr, *ptmp=nullptr, *pffn=nullptr;
    static MaskParam selfM, crossM;
    static bool initd = false;
    if (!initd) {
        cudaGetSymbolAddress((void**)&px,    g_x);
        cudaGetSymbolAddress((void**)&pxc,   g_xc);
        cudaGetSymbolAddress((void**)&pq,    g_q);
        cudaGetSymbolAddress((void**)&pk,    g_k);
        cudaGetSymbolAddress((void**)&pv,    g_v);
        cudaGetSymbolAddress((void**)&pattn, g_attn);
        cudaGetSymbolAddress((void**)&ptmp,  g_tmp);
        cudaGetSymbolAddress((void**)&pffn,  g_ffn);
        build_mask_host(SDEC, SDEC, 1u, selfM.rows);
        build_mask_host(SDEC, SENC, 2u, crossM.rows);
        initd = true;
    }

    const size_t DD = (size_t)DMODEL*DMODEL;   // per-layer weight stride
    dim3 gDec(12, 147);   // N=1536, M=18816
    dim3 gEnc(12, 158);   // N=1536, M=20160 (guarded)
    dim3 gFF1(24, 147);   // N=3072
    dim3 gAtt(NB, NH);

    // stage 0: inputs
    build_xc_kernel<<<(MENC*DMODEL + 255)/256, 256>>>(cross);
    build_x_ln_kernel<<<MDEC, 256>>>(x_dec, pos, val_w, val_b, pre_g, pre_b);

    // self attention
    sgemm_kernel<0><<<gDec, 256>>>(px, Wq,       bq,        pq, MDEC, DMODEL, DMODEL);
    sgemm_kernel<0><<<gDec, 256>>>(px, Wk,       bk,        pk, MDEC, DMODEL, DMODEL);
    sgemm_kernel<0><<<gDec, 256>>>(px, Wv,       bv,        pv, MDEC, DMODEL, DMODEL);
    attn_kernel<SDEC><<<gAtt, 256>>>(pq, pk, pv, pattn, selfM);
    sgemm_kernel<0><<<gDec, 256>>>(pattn, Wo,    bo,        ptmp, MDEC, DMODEL, DMODEL);
    add_ln_kernel<<<MDEC, 256>>>(px, ptmp, n1g, n1b);

    // cross attention
    sgemm_kernel<0><<<gDec, 256>>>(px,  Wq + DD, bq + DMODEL, pq, MDEC, DMODEL, DMODEL);
    sgemm_kernel<0><<<gEnc, 256>>>(pxc, Wk + DD, bk + DMODEL, pk, MENC, DMODEL, DMODEL);
    sgemm_kernel<0><<<gEnc, 256>>>(pxc, Wv + DD, bv + DMODEL, pv, MENC, DMODEL, DMODEL);
    attn_kernel<SENC><<<gAtt, 256>>>(pq, pk, pv, pattn, crossM);
    sgemm_kernel<0><<<gDec, 256>>>(pattn, Wo + DD, bo + DMODEL, ptmp, MDEC, DMODEL, DMODEL);
    add_ln_kernel<<<MDEC, 256>>>(px, ptmp, n2g, n2b);

    // FFN + final double LN
    sgemm_kernel<1><<<gFF1, 256>>>(px,   W1, b1, pffn, MDEC, DFFv,   DMODEL);
    sgemm_kernel<0><<<gDec, 256>>>(pffn, W2, b2, ptmp, MDEC, DMODEL, DFFv);
    add_ln2_kernel<<<MDEC, 256>>>(px, ptmp, n3g, n3b, fg, fb);

    // output + identity
    out_kernel<<<(Bv*Ev*SDEC*Pv*Cv + 255)/256, 256>>>(x_dec, val_w, val_b, out);
}

// round 6
// speedup vs baseline: 2.7637x; 2.7637x over previous
#include <cuda_runtime.h>
#include <cuda_bf16.h>
#include <cstdint>
#include <cmath>
#include <cstdlib>

// ---------------- static config ----------------
#define Bv 32
#define Cv 21
#define Pv 24
#define Ev 64
#define NB (Bv*Cv)          // 672 row-batches
#define SDEC 28
#define SENC 30
#define DMODEL 1536         // Pv*Ev
#define DFFv 3072
#define NH 8
#define DHh 192             // DMODEL/NH
#define MDEC (NB*SDEC)      // 18816 tokens
#define MENC (NB*SENC)      // 20160 tokens
#define LDEC 672

// ---------------- device scratch (static, allocation-free) ----------------
__device__ float g_x   [(size_t)MDEC*DMODEL];
__device__ float g_q   [(size_t)MDEC*DMODEL];
__device__ float g_k   [(size_t)MENC*DMODEL];
__device__ float g_v   [(size_t)MENC*DMODEL];
__device__ float g_tmp [(size_t)MDEC*DMODEL];

__device__ __nv_bfloat16 g_xbh[(size_t)MDEC*DMODEL],  g_xbl[(size_t)MDEC*DMODEL];
__device__ __nv_bfloat16 g_xcbh[(size_t)MENC*DMODEL], g_xcbl[(size_t)MENC*DMODEL];
__device__ __nv_bfloat16 g_abh[(size_t)MDEC*DMODEL],  g_abl[(size_t)MDEC*DMODEL];
__device__ __nv_bfloat16 g_fbh[(size_t)MDEC*DFFv],    g_fbl[(size_t)MDEC*DFFv];

#define DDsz ((size_t)DMODEL*DMODEL)
#define OFF_W1T (8*DDsz)
#define OFF_W2T (8*DDsz + (size_t)DMODEL*DFFv)
#define WT_TOTAL (8*DDsz + 2*(size_t)DMODEL*DFFv)
__device__ __nv_bfloat16 g_wth[WT_TOTAL], g_wtl[WT_TOTAL];

struct MaskParam { unsigned int rows[SDEC]; };

// ---------------- helpers ----------------
__device__ __forceinline__ uint32_t smem_to_u32(const void* p) {
    uint32_t a;
    asm("{ .reg .u64 t; cvta.to.shared.u64 t, %1; cvt.u32.u64 %0, t; }" : "=r"(a) : "l"(p));
    return a;
}
__device__ __forceinline__ void cpasync16(uint32_t dst, const void* src, unsigned sz) {
    asm volatile("cp.async.cg.shared.global [%0], [%1], 16, %2;" :: "r"(dst), "l"(src), "r"(sz));
}
__device__ __forceinline__ void ldsm4(uint32_t addr, uint32_t* r) {
    asm volatile("ldmatrix.sync.aligned.m8n8.x4.shared.b16 {%0,%1,%2,%3}, [%4];"
        : "=r"(r[0]), "=r"(r[1]), "=r"(r[2]), "=r"(r[3]) : "r"(addr));
}
__device__ __forceinline__ void mma16816(float* c, const uint32_t* a, const uint32_t* b) {
    asm volatile("mma.sync.aligned.m16n8k16.row.col.f32.bf16.bf16.f32 "
        "{%0,%1,%2,%3}, {%4,%5,%6,%7}, {%8,%9}, {%0,%1,%2,%3};"
        : "+f"(c[0]), "+f"(c[1]), "+f"(c[2]), "+f"(c[3])
        : "r"(a[0]), "r"(a[1]), "r"(a[2]), "r"(a[3]), "r"(b[0]), "r"(b[1]));
}
__device__ __forceinline__ void split_bf16(float v, __nv_bfloat16& h, __nv_bfloat16& l) {
    h = __float2bfloat16(v);
    l = __float2bfloat16(v - __bfloat162float(h));
}
__device__ __forceinline__ float blockReduceSum(float val, float* sh) {
    int lane = threadIdx.x & 31, wid = threadIdx.x >> 5;
    #pragma unroll
    for (int o = 16; o > 0; o >>= 1) val += __shfl_down_sync(0xffffffffu, val, o);
    if (lane == 0) sh[wid] = val;
    __syncthreads();
    if (wid == 0) {
        float v2 = (lane < 8) ? sh[lane] : 0.f;
        #pragma unroll
        for (int o = 4; o > 0; o >>= 1) v2 += __shfl_down_sync(0xffffffffu, v2, o);
        if (lane == 0) sh[0] = v2;
    }
    __syncthreads();
    float r = sh[0];
    __syncthreads();
    return r;
}

// ================= GEMM: C[M,N] = (Ah+Al)[M,K] @ (Bh+Bl)^T (B stored [N,K]) =================
// bf16x3 via mma.sync m16n8k16: AhBh + AhBl + AlBh, fp32 accum in registers.
// Tile 128x128, BK=32, 8 warps (2x4), warp tile 64x32, 2-stage cp.async.
#define STAGE_BYTES 32768
#define GSMEM_BYTES (2*STAGE_BYTES)
#define T_AH 0
#define T_AL 8192
#define T_BH 16384
#define T_BL 24576

__global__ void __launch_bounds__(256) gemm_bf16x3(
    const __nv_bfloat16* __restrict__ Ah, const __nv_bfloat16* __restrict__ Al,
    const __nv_bfloat16* __restrict__ Bh, const __nv_bfloat16* __restrict__ Bl,
    const float* __restrict__ bias, float* __restrict__ C,
    __nv_bfloat16* __restrict__ Chi, __nv_bfloat16* __restrict__ Clo,
    int M, int N, int K, int act)
{
    extern __shared__ char smem[];
    uint32_t sb = smem_to_u32(smem);
    const int tid = threadIdx.x, wid = tid >> 5, lane = tid & 31;
    const int m0 = blockIdx.y * 128, n0 = blockIdx.x * 128;
    const int wm = wid >> 2, wn = wid & 3;      // warp tile: rows wm*64, cols wn*32
    const int NK = K >> 5;

    float acc[4][4][4];
    #pragma unroll
    for (int a = 0; a < 4; a++)
        #pragma unroll
        for (int b = 0; b < 4; b++)
            #pragma unroll
            for (int c = 0; c < 4; c++) acc[a][b][c] = 0.f;

    auto load_stage = [&](int kc) {
        uint32_t base = sb + (kc & 1) * STAGE_BYTES;
        int k0 = kc << 5;
        #pragma unroll
        for (int t = 0; t < 8; t++) {
            int i = tid + t * 256;
            int tile = i >> 9, idx = i & 511;
            int r = idx >> 2, ch = idx & 3;
            uint32_t soff = base + tile * 8192 + r * 64 + ((ch ^ ((r >> 1) & 3)) * 16);
            if (tile < 2) {
                int gr = m0 + r;
                bool ok = gr < M;
                const __nv_bfloat16* src = (tile == 0 ? Ah : Al) + (size_t)(ok ? gr : 0) * K + k0 + ch * 8;
                cpasync16(soff, src, ok ? 16u : 0u);
            } else {
                const __nv_bfloat16* src = (tile == 2 ? Bh : Bl) + (size_t)(n0 + r) * K + k0 + ch * 8;
                cpasync16(soff, src, 16u);
            }
        }
        asm volatile("cp.async.commit_group;" ::: "memory");
    };

    // ldmatrix address helpers (row/chunk include the XOR swizzle)
    const int a_lrow = lane & 15, a_lch = lane >> 4;                    // A frags
    const int b_lrow = ((lane >> 4) & 1) * 8 + (lane & 7);              // B frags
    const int b_lch = (lane >> 3) & 1;

    load_stage(0);

    for (int kc = 0; kc < NK; kc++) {
        if (kc + 1 < NK) {
            load_stage(kc + 1);
            asm volatile("cp.async.wait_group 1;" ::: "memory");
        } else {
            asm volatile("cp.async.wait_group 0;" ::: "memory");
        }
        __syncthreads();

        uint32_t base = sb + (kc & 1) * STAGE_BYTES;
        #pragma unroll
        for (int ks = 0; ks < 2; ks++) {
            uint32_t ah[4][4], al[4][4], bh[2][4], bl[2][4];
            // Ah fragments: 4 m-tiles of 16
            #pragma unroll
            for (int mi = 0; mi < 4; mi++) {
                int r = wm * 64 + mi * 16 + a_lrow;
                int ch = 2 * ks + a_lch;
                ldsm4(base + T_AH + r * 64 + ((ch ^ ((r >> 1) & 3)) * 16), ah[mi]);
            }
            // Bh fragments: 2 x4 loads cover 4 n8-tiles
            #pragma unroll
            for (int ni2 = 0; ni2 < 2; ni2++) {
                int r = wn * 32 + ni2 * 16 + b_lrow;
                int ch = 2 * ks + b_lch;
                ldsm4(base + T_BH + r * 64 + ((ch ^ ((r >> 1) & 3)) * 16), bh[ni2]);
            }
            #pragma unroll
            for (int mi = 0; mi < 4; mi++)
                #pragma unroll
                for (int ni = 0; ni < 4; ni++)
                    mma16816(acc[mi][ni], ah[mi], &bh[ni >> 1][(ni & 1) * 2]);
            // Bl
            #pragma unroll
            for (int ni2 = 0; ni2 < 2; ni2++) {
                int r = wn * 32 + ni2 * 16 + b_lrow;
                int ch = 2 * ks + b_lch;
                ldsm4(base + T_BL + r * 64 + ((ch ^ ((r >> 1) & 3)) * 16), bl[ni2]);
            }
            #pragma unroll
            for (int mi = 0; mi < 4; mi++)
                #pragma unroll
                for (int ni = 0; ni < 4; ni++)
                    mma16816(acc[mi][ni], ah[mi], &bl[ni >> 1][(ni & 1) * 2]);
            // Al
            #pragma unroll
            for (int mi = 0; mi < 4; mi++) {
                int r = wm * 64 + mi * 16 + a_lrow;
                int ch = 2 * ks + a_lch;
                ldsm4(base + T_AL + r * 64 + ((ch ^ ((r >> 1) & 3)) * 16), al[mi]);
            }
            #pragma unroll
            for (int mi = 0; mi < 4; mi++)
                #pragma unroll
                for (int ni = 0; ni < 4; ni++)
                    mma16816(acc[mi][ni], al[mi], &bh[ni >> 1][(ni & 1) * 2]);
        }
        __syncthreads();
    }

    // ---- epilogue: lane (l) holds rows (l>>2, l>>2+8), cols (l&3)*2,+1 per tile
    #pragma unroll
    for (int mi = 0; mi < 4; mi++) {
        #pragma unroll
        for (int half = 0; half < 2; half++) {
            int row = m0 + wm * 64 + mi * 16 + (lane >> 2) + half * 8;
            if (row >= M) continue;
            #pragma unroll
            for (int ni = 0; ni < 4; ni++) {
                int col = n0 + wn * 32 + ni * 8 + (lane & 3) * 2;
                float v0 = acc[mi][ni][half * 2 + 0] + bias[col];
                float v1 = acc[mi][ni][half * 2 + 1] + bias[col + 1];
                if (act == 1) {
                    float x0 = v0, x1 = v1;
                    v0 = 0.5f * x0 * (1.f + tanhf(0.7978845608028654f * (x0 + 0.044715f * x0 * x0 * x0)));
                    v1 = 0.5f * x1 * (1.f + tanhf(0.7978845608028654f * (x1 + 0.044715f * x1 * x1 * x1)));
                }
                if (C) {
                    *reinterpret_cast<float2*>(C + (size_t)row * N + col) = make_float2(v0, v1);
                }
                if (Chi) {
                    __nv_bfloat16 h0, l0, h1, l1;
                    split_bf16(v0, h0, l0);
                    split_bf16(v1, h1, l1);
                    size_t bo = (size_t)row * N + col;
                    *reinterpret_cast<uint32_t*>(Chi + bo) =
                        ((uint32_t)__bfloat16_as_ushort(h1) << 16) | __bfloat16_as_ushort(h0);
                    *reinterpret_cast<uint32_t*>(Clo + bo) =
                        ((uint32_t)__bfloat16_as_ushort(l1) << 16) | __bfloat16_as_ushort(l0);
                }
            }
        }
    }
}

// ================= weight transpose + bf16 split: W[K,N] -> T[N,K] hi/lo =================
__global__ void wsplit_kernel(const float* __restrict__ W, int K, int N,
                              __nv_bfloat16* __restrict__ Th, __nv_bfloat16* __restrict__ Tl) {
    __shared__ float t[32][33];
    int kb = blockIdx.y * 32, nb = blockIdx.x * 32;
    int tx = threadIdx.x & 31, ty = threadIdx.x >> 5;
    #pragma unroll
    for (int r = ty; r < 32; r += 8) t[r][tx] = W[(size_t)(kb + r) * N + nb + tx];
    __syncthreads();
    #pragma unroll
    for (int r = ty; r < 32; r += 8) {
        float v = t[tx][r];     // W[kb+tx][nb+r]
        __nv_bfloat16 h, l; split_bf16(v, h, l);
        size_t o = (size_t)(nb + r) * K + kb + tx;
        Th[o] = h; Tl[o] = l;
    }
}

// ================= elementwise kernels =================
__global__ void build_xc_kernel(const float* __restrict__ cross,
                                __nv_bfloat16* __restrict__ oh, __nv_bfloat16* __restrict__ ol) {
    int idx = blockIdx.x * blockDim.x + threadIdx.x;
    const int total = MENC * DMODEL;
    if (idx >= total) return;
    int d = idx % DMODEL, t = idx / DMODEL;
    int s = t % SENC, n = t / SENC;
    int b = n / Cv, c = n % Cv;
    int p = d >> 6, e = d & 63;
    float v = cross[(size_t)b*(Ev*SENC*Pv*Cv) + (size_t)e*(SENC*Pv*Cv) + s*(Pv*Cv) + p*Cv + c];
    __nv_bfloat16 h, l; split_bf16(v, h, l);
    oh[idx] = h; ol[idx] = l;
}

__global__ void build_x_ln_kernel(const float* __restrict__ x_dec,
                                  const float* __restrict__ pos,
                                  const float* __restrict__ val_w,
                                  const float* __restrict__ val_b,
                                  const float* __restrict__ gam,
                                  const float* __restrict__ bet,
                                  __nv_bfloat16* __restrict__ oh, __nv_bfloat16* __restrict__ ol) {
    __shared__ float sh[32];
    int r = blockIdx.x;
    int s = r % SDEC, n = r / SDEC;
    int b = n / Cv, c = n % Cv;
    int tid = threadIdx.x;
    float v[6]; float sum = 0.f;
    #pragma unroll
    for (int q = 0; q < 6; q++) {
        int d = tid + q*256;
        int p = d >> 6, e = d & 63;
        float xd  = x_dec[(size_t)b*(LDEC*Cv) + (s*Pv + p)*Cv + c];
        float emb = xd * val_w[e] + val_b[e];
        float ps  = pos[(size_t)e*(SDEC*Pv*Cv) + s*(Pv*Cv) + p*Cv + c];
        v[q] = emb + ps; sum += v[q];
    }
    float mean = blockReduceSum(sum, sh) * (1.f/DMODEL);
    float vs = 0.f;
    #pragma unroll
    for (int q = 0; q < 6; q++) { float d0 = v[q]-mean; vs += d0*d0; }
    float var = blockReduceSum(vs, sh) * (1.f/DMODEL);
    float inv = rsqrtf(var + 1e-5f);
    #pragma unroll
    for (int q = 0; q < 6; q++) {
        int d = tid + q*256;
        float y = (v[q]-mean)*inv*gam[d] + bet[d];
        size_t o = (size_t)r*DMODEL + d;
        g_x[o] = y;
        __nv_bfloat16 h, l; split_bf16(y, h, l);
        oh[o] = h; ol[o] = l;
    }
}

__global__ void add_ln_kernel(float* __restrict__ X, const float* __restrict__ Y,
                              const float* __restrict__ gam, const float* __restrict__ bet,
                              __nv_bfloat16* __restrict__ oh, __nv_bfloat16* __restrict__ ol) {
    __shared__ float sh[32];
    int r = blockIdx.x, tid = threadIdx.x;
    float v[6]; float sum = 0.f;
    #pragma unroll
    for (int q = 0; q < 6; q++) {
        int d = tid + q*256;
        v[q] = X[(size_t)r*DMODEL + d] + Y[(size_t)r*DMODEL + d];
        sum += v[q];
    }
    float mean = blockReduceSum(sum, sh) * (1.f/DMODEL);
    float vs = 0.f;
    #pragma unroll
    for (int q = 0; q < 6; q++) { float d0 = v[q]-mean; vs += d0*d0; }
    float var = blockReduceSum(vs, sh) * (1.f/DMODEL);
    float inv = rsqrtf(var + 1e-5f);
    #pragma unroll
    for (int q = 0; q < 6; q++) {
        int d = tid + q*256;
        float y = (v[q]-mean)*inv*gam[d] + bet[d];
        size_t o = (size_t)r*DMODEL + d;
        X[o] = y;
        __nv_bfloat16 h, l; split_bf16(y, h, l);
        oh[o] = h; ol[o] = l;
    }
}

__global__ void add_ln2_kernel(float* __restrict__ X, const float* __restrict__ Y,
                               const float* __restrict__ g3, const float* __restrict__ b3,
                               const float* __restrict__ fg, const float* __restrict__ fb) {
    __shared__ float sh[32];
    int r = blockIdx.x, tid = threadIdx.x;
    float v[6]; float sum = 0.f;
    #pragma unroll
    for (int q = 0; q < 6; q++) {
        int d = tid + q*256;
        v[q] = X[(size_t)r*DMODEL + d] + Y[(size_t)r*DMODEL + d];
        sum += v[q];
    }
    float mean = blockReduceSum(sum, sh) * (1.f/DMODEL);
    float vs = 0.f;
    #pragma unroll
    for (int q = 0; q < 6; q++) { float d0 = v[q]-mean; vs += d0*d0; }
    float var = blockReduceSum(vs, sh) * (1.f/DMODEL);
    float inv = rsqrtf(var + 1e-5f);
    float sum2 = 0.f;
    #pragma unroll
    for (int q = 0; q < 6; q++) {
        int d = tid + q*256;
        v[q] = (v[q]-mean)*inv*g3[d] + b3[d];
        sum2 += v[q];
    }
    float mean2 = blockReduceSum(sum2, sh) * (1.f/DMODEL);
    float vs2 = 0.f;
    #pragma unroll
    for (int q = 0; q < 6; q++) { float d0 = v[q]-mean2; vs2 += d0*d0; }
    float var2 = blockReduceSum(vs2, sh) * (1.f/DMODEL);
    float inv2 = rsqrtf(var2 + 1e-5f);
    #pragma unroll
    for (int q = 0; q < 6; q++) {
        int d = tid + q*256;
        X[(size_t)r*DMODEL + d] = (v[q]-mean2)*inv2*fg[d] + fb[d];
    }
}

__global__ void out_kernel(const float* __restrict__ x_dec,
                           const float* __restrict__ val_w,
                           const float* __restrict__ val_b,
                           float* __restrict__ out) {
    int idx = blockIdx.x * blockDim.x + threadIdx.x;
    const int total = Bv*Ev*SDEC*Pv*Cv;
    if (idx >= total) return;
    int c = idx % Cv;
    int p = (idx / Cv) % Pv;
    int s = (idx / (Cv*Pv)) % SDEC;
    int e = (idx / (Cv*Pv*SDEC)) % Ev;
    int b =  idx / (Cv*Pv*SDEC*Ev);
    int n = b*Cv + c;
    float xf  = g_x[(size_t)(n*SDEC + s)*DMODEL + p*Ev + e];
    float emb = x_dec[(size_t)b*(LDEC*Cv) + (s*Pv + p)*Cv + c] * val_w[e] + val_b[e];
    out[idx] = xf + emb;
}

// ================= sparse attention (fp32 in, bf16 pair out) =================
template<int LK>
__global__ void __launch_bounds__(256) attn_kernel(
    const float* __restrict__ Q, const float* __restrict__ Km,
    const float* __restrict__ Vm,
    __nv_bfloat16* __restrict__ Oh, __nv_bfloat16* __restrict__ Ol, MaskParam mask)
{
    __shared__ float qs[DHh][SDEC];
    __shared__ float ks[LK][DHh];
    __shared__ float sc[SDEC][32];
    int n = blockIdx.x, h = blockIdx.y, tid = threadIdx.x;
    const float* qb = Q  + (size_t)n*SDEC*DMODEL + h*DHh;
    const float* kb = Km + (size_t)n*LK  *DMODEL + h*DHh;
    const float* vb = Vm + (size_t)n*LK  *DMODEL + h*DHh;

    for (int idx = tid; idx < SDEC*DHh; idx += 256) {
        int i = idx / DHh, d = idx % DHh;
        qs[d][i] = qb[(size_t)i*DMODEL + d];
    }
    for (int idx = tid; idx < LK*DHh; idx += 256) {
        int j = idx / DHh, d = idx % DHh;
        ks[j][d] = kb[(size_t)j*DMODEL + d];
    }
    __syncthreads();

    const float scale = 0.07216878364870323f;   // 1/sqrt(192)
    for (int idx = tid; idx < SDEC*LK; idx += 256) {
        int i = idx % SDEC, j = idx / SDEC;
        float s = 0.f;
        #pragma unroll 16
        for (int d = 0; d < DHh; d++) s += qs[d][i] * ks[j][d];
        bool mm = (mask.rows[i] >> j) & 1u;
        sc[i][j] = mm ? s*scale : -1e9f;
    }
    __syncthreads();

    if (tid < SDEC) {
        float mx = -3.0e38f;
        #pragma unroll
        for (int j = 0; j < LK; j++) mx = fmaxf(mx, sc[tid][j]);
        float ssum = 0.f;
        #pragma unroll
        for (int j = 0; j < LK; j++) { float e0 = expf(sc[tid][j]-mx); sc[tid][j] = e0; ssum += e0; }
        float invs = 1.f/ssum;
        #pragma unroll
        for (int j = 0; j < LK; j++) sc[tid][j] *= invs;
    }
    __syncthreads();

    for (int idx = tid; idx < SDEC*DHh; idx += 256) {
        int i = idx / DHh, d = idx % DHh;
        float o = 0.f;
        #pragma unroll
        for (int j = 0; j < LK; j++) o += sc[i][j] * vb[(size_t)j*DMODEL + d];
        size_t oo = (size_t)(n*SDEC + i)*DMODEL + h*DHh + d;
        __nv_bfloat16 hh, ll; split_bf16(o, hh, ll);
        Oh[oo] = hh; Ol[oo] = ll;
    }
}

// ---------------- host: numpy default_rng(seed).random() bit-exact ----------------
typedef unsigned __int128 u128;
struct PCG64H { u128 state, inc; };
static inline void pcg_step(PCG64H& r) {
    const u128 MULT = (((u128)0x2360ed051fc65da4ULL) << 64) | 0x4385df649fccf645ULL;
    r.state = r.state * MULT + r.inc;
}
static inline uint64_t pcg_next(PCG64H& r) {
    pcg_step(r);
    uint64_t xored = (uint64_t)(r.state >> 64) ^ (uint64_t)r.state;
    unsigned rot = (unsigned)(r.state >> 122);
    return (xored >> rot) | (xored << ((64u - rot) & 63u));
}
static void np_seed_pcg(uint32_t seed_word, PCG64H& r) {
    const uint32_t INIT_A = 0x43b0d7e5u, MULT_A = 0x931e8875u;
    const uint32_t INIT_B = 0x8b51f9ddu, MULT_B = 0x58f38dedu;
    const uint32_t MIX_L  = 0xca01f9ddu, MIX_R  = 0x4973f715u;
    uint32_t hc = INIT_A;
    uint32_t pool[4];
    auto hashmix = [&hc, MULT_A](uint32_t v) -> uint32_t {
        v ^= hc; hc *= MULT_A; v *= hc; v ^= v >> 16; return v;
    };
    auto mix = [MIX_L, MIX_R](uint32_t x, uint32_t y) -> uint32_t {
        uint32_t res = x*MIX_L - y*MIX_R; res ^= res >> 16; return res;
    };
    pool[0] = hashmix(seed_word);
    for (int i = 1; i < 4; i++) pool[i] = hashmix(0u);
    for (int s = 0; s < 4; s++)
        for (int d = 0; d < 4; d++)
            if (s != d) pool[d] = mix(pool[d], hashmix(pool[s]));
    uint32_t st[8]; uint32_t hc2 = INIT_B;
    for (int i = 0; i < 8; i++) {
        uint32_t v = pool[i & 3];
        v ^= hc2; hc2 *= MULT_B; v *= hc2; v ^= v >> 16;
        st[i] = v;
    }
    uint64_t w[4];
    for (int i = 0; i < 4; i++) w[i] = (uint64_t)st[2*i] | ((uint64_t)st[2*i+1] << 32);
    u128 initstate = (((u128)w[0]) << 64) | w[1];
    u128 initseq   = (((u128)w[2]) << 64) | w[3];
    r.state = 0; r.inc = (initseq << 1) | 1;
    pcg_step(r);
    r.state += initstate;
    pcg_step(r);
}
static void build_mask_host(int Lq, int Lk, uint32_t seed, unsigned int* rows) {
    PCG64H r; np_seed_pcg(seed, r);
    int off = Lk - Lq;
    for (int i = 0; i < Lq; i++) {
        unsigned int m = 0;
        for (int j = 0; j < Lk; j++) {
            double dv = (double)(pcg_next(r) >> 11) * (1.0/9007199254740992.0);
            int a = i + off - j; if (a < 0) a = -a;
            if ((a <= 3) || ((j & 3) == 0) || (dv < 0.1)) m |= (1u << j);
        }
        rows[i] = m;
    }
}

// ---------------- launch ----------------
extern "C" void kernel_launch(void* const* d_in, const int* in_sizes, int n_in,
                              void* d_out, int out_size) {
    const float* x_dec = (const float*)d_in[0];
    const float* cross = (const float*)d_in[1];
    const float* val_w = (const float*)d_in[2];
    const float* val_b = (const float*)d_in[3];
    const float* pos   = (const float*)d_in[4];
    const float* pre_g = (const float*)d_in[5];
    const float* pre_b = (const float*)d_in[6];
    const float* Wq = (const float*)d_in[7];
    const float* bq = (const float*)d_in[8];
    const float* Wk = (const float*)d_in[9];
    const float* bk = (const float*)d_in[10];
    const float* Wv = (const float*)d_in[11];
    const float* bv = (const float*)d_in[12];
    const float* Wo = (const float*)d_in[13];
    const float* bo = (const float*)d_in[14];
    const float* n1g = (const float*)d_in[15];
    const float* n1b = (const float*)d_in[16];
    const float* n2g = (const float*)d_in[17];
    const float* n2b = (const float*)d_in[18];
    const float* n3g = (const float*)d_in[19];
    const float* n3b = (const float*)d_in[20];
    const float* W1 = (const float*)d_in[21];
    const float* b1 = (const float*)d_in[22];
    const float* W2 = (const float*)d_in[23];
    const float* b2 = (const float*)d_in[24];
    const float* fg = (const float*)d_in[25];
    const float* fb = (const float*)d_in[26];
    float* out = (float*)d_out;

    static float *px=nullptr, *pq=nullptr, *pk=nullptr, *pv=nullptr, *ptmp=nullptr;
    static __nv_bfloat16 *xbh, *xbl, *xcbh, *xcbl, *abh, *abl, *fbh, *fbl, *wth, *wtl;
    static MaskParam selfM, crossM;
    static bool initd = false;
    if (!initd) {
        cudaGetSymbolAddress((void**)&px,   g_x);
        cudaGetSymbolAddress((void**)&pq,   g_q);
        cudaGetSymbolAddress((void**)&pk,   g_k);
        cudaGetSymbolAddress((void**)&pv,   g_v);
        cudaGetSymbolAddress((void**)&ptmp, g_tmp);
        cudaGetSymbolAddress((void**)&xbh,  g_xbh);
        cudaGetSymbolAddress((void**)&xbl,  g_xbl);
        cudaGetSymbolAddress((void**)&xcbh, g_xcbh);
        cudaGetSymbolAddress((void**)&xcbl, g_xcbl);
        cudaGetSymbolAddress((void**)&abh,  g_abh);
        cudaGetSymbolAddress((void**)&abl,  g_abl);
        cudaGetSymbolAddress((void**)&fbh,  g_fbh);
        cudaGetSymbolAddress((void**)&fbl,  g_fbl);
        cudaGetSymbolAddress((void**)&wth,  g_wth);
        cudaGetSymbolAddress((void**)&wtl,  g_wtl);
        build_mask_host(SDEC, SDEC, 1u, selfM.rows);
        build_mask_host(SDEC, SENC, 2u, crossM.rows);
        cudaFuncSetAttribute(gemm_bf16x3, cudaFuncAttributeMaxDynamicSharedMemorySize, GSMEM_BYTES);
        initd = true;
    }

    const size_t DD = DDsz;
    dim3 gW(DMODEL/32, DMODEL/32);
    dim3 gAtt(NB, NH);
    dim3 gDec(12, 147);   // N=1536/128, M=18816/128
    dim3 gEnc(12, 158);   // M=20160 (ragged last tile)
    dim3 gFF1(24, 147);   // N=3072/128
    dim3 gFF2(12, 147);

    // ---- weight transpose + split (input-dependent, every call)
    wsplit_kernel<<<gW, 256>>>(Wq,        DMODEL, DMODEL, wth + 0*DD, wtl + 0*DD);
    wsplit_kernel<<<gW, 256>>>(Wk,        DMODEL, DMODEL, wth + 1*DD, wtl + 1*DD);
    wsplit_kernel<<<gW, 256>>>(Wv,        DMODEL, DMODEL, wth + 2*DD, wtl + 2*DD);
    wsplit_kernel<<<gW, 256>>>(Wo,        DMODEL, DMODEL, wth + 3*DD, wtl + 3*DD);
    wsplit_kernel<<<gW, 256>>>(Wq + DD,   DMODEL, DMODEL, wth + 4*DD, wtl + 4*DD);
    wsplit_kernel<<<gW, 256>>>(Wk + DD,   DMODEL, DMODEL, wth + 5*DD, wtl + 5*DD);
    wsplit_kernel<<<gW, 256>>>(Wv + DD,   DMODEL, DMODEL, wth + 6*DD, wtl + 6*DD);
    wsplit_kernel<<<gW, 256>>>(Wo + DD,   DMODEL, DMODEL, wth + 7*DD, wtl + 7*DD);
    wsplit_kernel<<<dim3(DFFv/32, DMODEL/32), 256>>>(W1, DMODEL, DFFv, wth + OFF_W1T, wtl + OFF_W1T);
    wsplit_kernel<<<dim3(DMODEL/32, DFFv/32), 256>>>(W2, DFFv, DMODEL, wth + OFF_W2T, wtl + OFF_W2T);

    // ---- inputs
    build_xc_kernel<<<(MENC*DMODEL + 255)/256, 256>>>(cross, xcbh, xcbl);
    build_x_ln_kernel<<<MDEC, 256>>>(x_dec, pos, val_w, val_b, pre_g, pre_b, xbh, xbl);

    // ---- self attention
    gemm_bf16x3<<<gDec, 256, GSMEM_BYTES>>>(xbh, xbl, wth + 0*DD, wtl + 0*DD, bq, pq, nullptr, nullptr, MDEC, DMODEL, DMODEL, 0);
    gemm_bf16x3<<<gDec, 256, GSMEM_BYTES>>>(xbh, xbl, wth + 1*DD, wtl + 1*DD, bk, pk, nullptr, nullptr, MDEC, DMODEL, DMODEL, 0);
    gemm_bf16x3<<<gDec, 256, GSMEM_BYTES>>>(xbh, xbl, wth + 2*DD, wtl + 2*DD, bv, pv, nullptr, nullptr, MDEC, DMODEL, DMODEL, 0);
    attn_kernel<SDEC><<<gAtt, 256>>>(pq, pk, pv, abh, abl, selfM);
    gemm_bf16x3<<<gDec, 256, GSMEM_BYTES>>>(abh, abl, wth + 3*DD, wtl + 3*DD, bo, ptmp, nullptr, nullptr, MDEC, DMODEL, DMODEL, 0);
    add_ln_kernel<<<MDEC, 256>>>(px, ptmp, n1g, n1b, xbh, xbl);

    // ---- cross attention
    gemm_bf16x3<<<gDec, 256, GSMEM_BYTES>>>(xbh,  xbl,  wth + 4*DD, wtl + 4*DD, bq + DMODEL, pq, nullptr, nullptr, MDEC, DMODEL, DMODEL, 0);
    gemm_bf16x3<<<gEnc, 256, GSMEM_BYTES>>>(xcbh, xcbl, wth + 5*DD, wtl + 5*DD, bk + DMODEL, pk, nullptr, nullptr, MENC, DMODEL, DMODEL, 0);
    gemm_bf16x3<<<gEnc, 256, GSMEM_BYTES>>>(xcbh, xcbl, wth + 6*DD, wtl + 6*DD, bv + DMODEL, pv, nullptr, nullptr, MENC, DMODEL, DMODEL, 0);
    attn_kernel<SENC><<<gAtt, 256>>>(pq, pk, pv, abh, abl, crossM);
    gemm_bf16x3<<<gDec, 256, GSMEM_BYTES>>>(abh, abl, wth + 7*DD, wtl + 7*DD, bo + DMODEL, ptmp, nullptr, nullptr, MDEC, DMODEL, DMODEL, 0);
    add_ln_kernel<<<MDEC, 256>>>(px, ptmp, n2g, n2b, xbh, xbl);

    // ---- FFN + final double LN
    gemm_bf16x3<<<gFF1, 256, GSMEM_BYTES>>>(xbh, xbl, wth + OFF_W1T, wtl + OFF_W1T, b1, nullptr, fbh, fbl, MDEC, DFFv, DMODEL, 1);
    gemm_bf16x3<<<gFF2, 256, GSMEM_BYTES>>>(fbh, fbl, wth + OFF_W2T, wtl + OFF_W2T, b2, ptmp, nullptr, nullptr, MDEC, DMODEL, DFFv, 0);
    add_ln2_kernel<<<MDEC, 256>>>(px, ptmp, n3g, n3b, fg, fb);

    // ---- output + identity
    out_kernel<<<(Bv*Ev*SDEC*Pv*Cv + 255)/256, 256>>>(x_dec, val_w, val_b, out);
}